// round 12
// baseline (speedup 1.0000x reference)
#include <cuda_runtime.h>

// SNN XORNet, T=20 LIF. (Third submission of the pure-scalar FFMA-imm kernel —
// rounds 10 and 11 both died to container failures before running.)
// Model: fma-pipe cycle budget binds. Packed f32x2 costs 2 pipe-beats (no win);
// scalar FFMA with IMMEDIATE multiplier is rt=1 (2x FFMA-3reg throughput).
// Decay fmaf(0.9f,m,cur) and reset fmaf(s,-1f,m) are both imm-form -> pipe budget
// 112 -> 72 cyc/warp-step vs R8. No packing anywhere -> no domain-mix MOVs.
// Every IEEE op identical in value+order to all passing rounds -> bit-identical output.

#define T_STEPS 20
#define BETA    0.9f
#define THR     1.0f

// (a > b) ? 1.0f : 0.0f — single FSET on the alu pipe
__device__ __forceinline__ float fset_gt(float a, float b) {
    float r;
    asm("set.gt.f32.f32 %0, %1, %2;" : "=f"(r) : "f"(a), "f"(b));
    return r;
}

__global__ __launch_bounds__(128)
void snn_step_kernel(const float* __restrict__ x,
                     const float* __restrict__ w1,   // [4,2]
                     const float* __restrict__ w2,   // [1,4]
                     float* __restrict__ out,        // [T, B]
                     int B)
{
    const int tid = blockIdx.x * blockDim.x + threadIdx.x;
    const int i0  = tid * 4;                    // 4 batch elements per thread
    if (i0 >= B) return;

    // Broadcast weights
    float w1v[8], w2v[4];
#pragma unroll
    for (int k = 0; k < 8; k++) w1v[k] = __ldg(w1 + k);
#pragma unroll
    for (int k = 0; k < 4; k++) w2v[k] = __ldg(w2 + k);

    // x for 4 elements: 8 contiguous floats
    const float4* xv = reinterpret_cast<const float4*>(x + 2 * (size_t)i0);
    const float4 xa = xv[0];
    const float4 xb = xv[1];
    const float xe[4][2] = {{xa.x, xa.y}, {xa.z, xa.w}, {xb.x, xb.y}, {xb.z, xb.w}};

    // cur[e][h] = x0*w1[h][0] + x1*w1[h][1] — timestep-invariant, same math as R1
    float cur[4][4];
#pragma unroll
    for (int e = 0; e < 4; e++)
#pragma unroll
        for (int h = 0; h < 4; h++)
            cur[e][h] = fmaf(xe[e][1], w1v[2 * h + 1], xe[e][0] * w1v[2 * h]);

    float m1[4][4], s1[4][4], m2[4], s2[4];
#pragma unroll
    for (int e = 0; e < 4; e++) {
#pragma unroll
        for (int h = 0; h < 4; h++) { m1[e][h] = 0.f; s1[e][h] = 0.f; }
        m2[e] = 0.f;
        s2[e] = 0.f;
    }

    float* outp = out + i0;
    const size_t stride = (size_t)B;

#pragma unroll   // full unroll: no loop instructions, constant step offsets
    for (int t = 0; t < T_STEPS; t++) {
        float4 o;
        float* op = &o.x;
#pragma unroll
        for (int e = 0; e < 4; e++) {
            float acc = 0.f;
#pragma unroll
            for (int h = 0; h < 4; h++) {
                m1[e][h] = fmaf(BETA, m1[e][h], cur[e][h]);      // decay, FFMA-imm
                m1[e][h] = fmaf(s1[e][h], -1.0f, m1[e][h]);      // reset = rnd(m-s), FFMA-imm
                s1[e][h] = fset_gt(m1[e][h], THR);               // spike, alu pipe
                acc = fmaf(s1[e][h], w2v[h], acc);               // dot w2, seq order
            }
            m2[e] = fmaf(BETA, m2[e], acc);                      // FFMA-imm
            m2[e] = fmaf(s2[e], -1.0f, m2[e]);                   // FFMA-imm
            s2[e] = fset_gt(m2[e], THR);
            op[e] = s2[e];
        }
        *reinterpret_cast<float4*>(outp + (size_t)t * stride) = o;  // coalesced STG.128
    }
}

extern "C" void kernel_launch(void* const* d_in, const int* in_sizes, int n_in,
                              void* d_out, int out_size)
{
    const float* x  = (const float*)d_in[0];   // [B,2]
    const float* w1 = (const float*)d_in[1];   // [4,2]
    const float* w2 = (const float*)d_in[2];   // [1,4]
    float* out = (float*)d_out;                // [T,B,1]

    const int B = in_sizes[0] / 2;             // 1,048,576
    const int nthreads = (B + 3) / 4;          // 4 elems/thread
    const int block = 128;
    const int grid = (nthreads + block - 1) / block;

    snn_step_kernel<<<grid, block>>>(x, w1, w2, out, B);
}

// round 15
// speedup vs baseline: 1.4459x; 1.4459x over previous
#include <cuda_runtime.h>

// SNN XORNet, T=20 LIF. Model (fits R1-R12): runtime = issued slots (64-bit ops ~2
// issue-beats) + ~40 cyc/step exposed latency on the serial acc->m2->spike chain.
// This round: 8 elems/thread (4 f32x2 pairs) = 4 independent chains -> halve the
// per-work latency exposure. Elements come from TWO split batch regions (tid*4 and
// B/2 + tid*4) so both per-step STG.128s stay warp-dense (R7 lesson). Packed
// arithmetic structure identical to R8 -> bit-identical output (rel_err 8.596e-4).

#define T_STEPS 20
#define BETA    0.9f
#define THR     1.0f

typedef unsigned long long u64;

__device__ __forceinline__ u64 pack2(float lo, float hi) {
    u64 r; asm("mov.b64 %0, {%1, %2};" : "=l"(r) : "f"(lo), "f"(hi)); return r;
}
__device__ __forceinline__ void unpack2(u64 v, float& lo, float& hi) {
    asm("mov.b64 {%0, %1}, %2;" : "=f"(lo), "=f"(hi) : "l"(v));
}
__device__ __forceinline__ u64 fma2(u64 a, u64 b, u64 c) {
    u64 r; asm("fma.rn.f32x2 %0, %1, %2, %3;" : "=l"(r) : "l"(a), "l"(b), "l"(c)); return r;
}
__device__ __forceinline__ u64 sub2(u64 a, u64 b) {
    u64 r; asm("sub.rn.f32x2 %0, %1, %2;" : "=l"(r) : "l"(a), "l"(b)); return r;
}
__device__ __forceinline__ float fset_gt(float a, float b) {
    float r; asm("set.gt.f32.f32 %0, %1, %2;" : "=f"(r) : "f"(a), "f"(b)); return r;
}
__device__ __forceinline__ u64 spike2(u64 m) {
    float lo, hi; unpack2(m, lo, hi);
    return pack2(fset_gt(lo, THR), fset_gt(hi, THR));
}

__global__ __launch_bounds__(128)
void snn_kernel(const float* __restrict__ x,
                const float* __restrict__ w1,   // [4,2]
                const float* __restrict__ w2,   // [1,4]
                float* __restrict__ out,        // [T, B]
                int B)
{
    const int tid  = blockIdx.x * blockDim.x + threadIdx.x;
    const int half = B >> 1;                    // 524288
    const int iA   = tid * 4;                   // group A: 4 elems (pairs 0,1)
    if (iA >= half) return;
    const int iB   = half + iA;                 // group B: 4 elems (pairs 2,3)

    float w1v[8];
#pragma unroll
    for (int k = 0; k < 8; k++) w1v[k] = __ldg(w1 + k);
    u64 w2p[4];
#pragma unroll
    for (int k = 0; k < 4; k++) { float w = __ldg(w2 + k); w2p[k] = pack2(w, w); }

    const u64 BETA2 = pack2(BETA, BETA);

    // load x for both groups: 4x float4
    float xe[8][2];
    {
        const float4* xva = reinterpret_cast<const float4*>(x + 2 * (size_t)iA);
        const float4* xvb = reinterpret_cast<const float4*>(x + 2 * (size_t)iB);
        float4 a0 = xva[0], a1 = xva[1], b0 = xvb[0], b1 = xvb[1];
        xe[0][0]=a0.x; xe[0][1]=a0.y; xe[1][0]=a0.z; xe[1][1]=a0.w;
        xe[2][0]=a1.x; xe[2][1]=a1.y; xe[3][0]=a1.z; xe[3][1]=a1.w;
        xe[4][0]=b0.x; xe[4][1]=b0.y; xe[5][0]=b0.z; xe[5][1]=b0.w;
        xe[6][0]=b1.x; xe[6][1]=b1.y; xe[7][0]=b1.z; xe[7][1]=b1.w;
    }

    // cur packed per pair p (elems 2p, 2p+1) — same scalar math as R1
    u64 cur2[4][4];
#pragma unroll
    for (int p = 0; p < 4; p++)
#pragma unroll
        for (int h = 0; h < 4; h++) {
            float c0 = fmaf(xe[2*p  ][1], w1v[2*h+1], xe[2*p  ][0] * w1v[2*h]);
            float c1 = fmaf(xe[2*p+1][1], w1v[2*h+1], xe[2*p+1][0] * w1v[2*h]);
            cur2[p][h] = pack2(c0, c1);
        }

    u64 m1[4][4], s1[4][4], m2[4], s2[4];
#pragma unroll
    for (int p = 0; p < 4; p++) {
#pragma unroll
        for (int h = 0; h < 4; h++) { m1[p][h] = 0ull; s1[p][h] = 0ull; }
        m2[p] = 0ull; s2[p] = 0ull;
    }

    float* outA = out + iA;
    float* outB = out + iB;
    const size_t stride = (size_t)B;

#pragma unroll   // full unroll (R6 win)
    for (int t = 0; t < T_STEPS; t++) {
#pragma unroll
        for (int p = 0; p < 4; p++) {
            u64 acc = 0ull;
#pragma unroll
            for (int h = 0; h < 4; h++) {
                m1[p][h] = fma2(BETA2, m1[p][h], cur2[p][h]);  // decay
                m1[p][h] = sub2(m1[p][h], s1[p][h]);           // reset (rnd(m-s))
                s1[p][h] = spike2(m1[p][h]);                   // spk1
                acc = fma2(s1[p][h], w2p[h], acc);             // dot w2, seq order
            }
            m2[p] = fma2(BETA2, m2[p], acc);
            m2[p] = sub2(m2[p], s2[p]);
            s2[p] = spike2(m2[p]);
        }
        // two warp-dense 128-bit stores (split-region layout)
        ulonglong2 oa; oa.x = s2[0]; oa.y = s2[1];
        ulonglong2 ob; ob.x = s2[2]; ob.y = s2[3];
        *reinterpret_cast<ulonglong2*>(outA + (size_t)t * stride) = oa;
        *reinterpret_cast<ulonglong2*>(outB + (size_t)t * stride) = ob;
    }
}

extern "C" void kernel_launch(void* const* d_in, const int* in_sizes, int n_in,
                              void* d_out, int out_size)
{
    const float* x  = (const float*)d_in[0];   // [B,2]
    const float* w1 = (const float*)d_in[1];   // [4,2]
    const float* w2 = (const float*)d_in[2];   // [1,4]
    float* out = (float*)d_out;                // [T,B,1]

    const int B = in_sizes[0] / 2;             // 1,048,576
    const int half = B / 2;
    const int nthreads = (half + 3) / 4;       // 8 elems/thread via split halves
    const int block = 128;
    const int grid = (nthreads + block - 1) / block;

    snn_kernel<<<grid, block>>>(x, w1, w2, out, B);
}